// round 16
// baseline (speedup 1.0000x reference)
#include <cuda_runtime.h>

#define N_NODES 10000
#define N_EDGES 320000
#define QUADS (N_EDGES / 4)      // 80000 per GSO
#define OCTS_PER_GSO (N_EDGES / 8)  // 40000
#define NOCT (2 * OCTS_PER_GSO)     // 80000
#define NB 148
#define NT 1024
#define BM_WORDS 320
#define DC 68       // P4 dot chunk: 148 blocks x 68 >= 10000
#define DC5 76      // P5' dot chunk: 132 blocks x 76 >= 10000
#define OPB 541     // octs per block: 148*541 >= 80000 (last block partial)

// INVARIANT: accumulated scratch (CL*, bm*, D, sig) is ZERO at kernel entry
// and restored to ZERO before exit. L1-cached __ldg of data written earlier in
// this launch is safe: L1 is flushed at launch boundaries, global stores and
// atomics don't allocate in L1, and no array is regular-loaded before its
// producer phase's barrier. Each thread owns ONE oct (8 edges, single GSO) in
// every scan phase; its packed coords live in registers for the whole kernel.
__device__ float2 g_CL1[N_NODES];      // {R1, R2}
__device__ float4 g_CL2[N_NODES];      // {R3, R5, R4, R6}
__device__ float2 g_CL3p[2][N_NODES];  // GSO0: {R7, R11}; GSO1: {R8, R12}  (lvl4 gathers)
__device__ float  g_CL3s[2][N_NODES];  // GSO0: R10;       GSO1: R9        (dot only)
__device__ float4 g_CL4[N_NODES];      // {R13, R15, R14, R16}
__device__ unsigned g_bm1[BM_WORDS];
__device__ unsigned g_bm2[BM_WORDS];
__device__ float g_D[17][4][64];
__device__ float g_sig[5];
__device__ int g_count;             // returns to 0 at each barrier
__device__ volatile int g_gen;      // monotonic; equality-compare only

__constant__ int c_VEC_ID[5][5] = {
    {0, 1, 3, 2, 6},
    {1, 3, 7, 4, 9},
    {3, 7, 13, 8, 14},
    {2, 5, 10, 6, 12},
    {6, 11, 15, 12, 16}};
// pool slots: CL1.xy, CL2.xyzw, CL3p0.xy, CL3s0, CL3p1.xy, CL3s1, CL4.xyzw
__constant__ int c_SVID[16] = {1, 2, 3, 5, 4, 6, 7, 11, 10, 8, 12, 9, 13, 15, 14, 16};
__constant__ int c_PC2A[4] = {0, 1, 3, 4};  // early-epilogue pc2 (si in {0,1,0,3})

__device__ __forceinline__ void red1(float* p, float a) {
    asm volatile("red.global.add.f32 [%0], %1;" :: "l"(p), "f"(a) : "memory");
}
__device__ __forceinline__ void red2(float* p, float a, float b) {
    asm volatile("red.global.add.v2.f32 [%0], {%1,%2};" :: "l"(p), "f"(a), "f"(b) : "memory");
}

__device__ __forceinline__ void barrier_arrive(int target) {
    __syncthreads();
    if (threadIdx.x == 0) {
        __threadfence();
        int gen = g_gen;
        if (atomicAdd(&g_count, 1) == target - 1) {
            g_count = 0;
            __threadfence();
            g_gen = gen + 1;
        }
    }
}
__device__ __forceinline__ void barrier_wait(int target) {
    __syncthreads();
    if (threadIdx.x == 0) {
        __threadfence();
        int gen = g_gen;
        if (atomicAdd(&g_count, 1) == target - 1) {
            g_count = 0;
            __threadfence();
            g_gen = gen + 1;
        } else {
            while (g_gen == gen) { }
        }
    }
    __syncthreads();
}

// Full epilogue unit for one (b, pc2): T[si] in smem, then out += T @ W2[pc2].
__device__ __forceinline__ void epi_unit(
    int b, int pc2, const float* __restrict__ x,
    const float* __restrict__ W1, const float* __restrict__ b1,
    const float* __restrict__ W2, float* __restrict__ out, float* pool) {
    int e2 = pc2 / 3, k2 = pc2 % 3;
    int si = (k2 == 0) ? 0 : (e2 * 2 + k2);
    float sg = (si == 0) ? 1.0f : __ldg(&g_sig[si]);
    int g = threadIdx.x & 127, fo = threadIdx.x >> 7;  // 8 f-groups
    float* Tl = pool + 1024;
    float acc = 0.f;
#pragma unroll
    for (int pc1 = 0; pc1 < 6; pc1++) {
        int e1 = pc1 / 3, k1 = pc1 % 3;
        int pi = (k1 == 0) ? 0 : (e1 * 2 + k1);
        int vid = c_VEC_ID[si][pi];
        const float* Dp = vid ? &g_D[vid][b][0] : (x + (size_t)b * N_NODES * 64);
        const float* Wp = W1 + (size_t)pc1 * 64 * 128;
#pragma unroll
        for (int i = 0; i < 8; i++) {
            int f = fo * 8 + i;
            acc += __ldg(Dp + f) * __ldg(Wp + (size_t)f * 128 + g);
        }
    }
    pool[fo * 128 + g] = acc;
    __syncthreads();
    if (fo == 0) {
        float s = sg * __ldg(b1 + g);
#pragma unroll
        for (int i = 0; i < 8; i++) s += pool[i * 128 + g];
        Tl[g] = s;
    }
    __syncthreads();
    const float* Wp2 = W2 + (size_t)pc2 * 128 * 128;
    float acc2 = 0.f;
#pragma unroll
    for (int i = 0; i < 16; i++) {
        int f = fo * 16 + i;
        acc2 += Tl[f] * __ldg(Wp2 + (size_t)f * 128 + g);
    }
    __syncthreads();
    pool[fo * 128 + g] = acc2;
    __syncthreads();
    if (fo == 0) {
        float s = 0.f;
#pragma unroll
        for (int i = 0; i < 8; i++) s += pool[i * 128 + g];
        atomicAdd(out + (size_t)b * 128 + g, s);
    }
}

__global__ void __launch_bounds__(NT, 1)
fused_kernel(const int* __restrict__ eidx, const float* __restrict__ evals,
             const float* __restrict__ x,
             const float* __restrict__ W1, const float* __restrict__ b1,
             const float* __restrict__ W2, const float* __restrict__ b2,
             float* __restrict__ out) {
    __shared__ __align__(16) float pool[1920];
    __shared__ unsigned sbm[BM_WORDS];

    const int tid = threadIdx.x;
    const int blk = blockIdx.x;
    const float4 z4 = make_float4(0.f, 0.f, 0.f, 0.f);

    // One oct (8 edges, quads jq and jq+1, single GSO) per thread, all phases.
    const int ostart = blk * OPB;
    const int ocount = min(OPB, NOCT - ostart);
    const bool act = tid < ocount;
    const int oct = ostart + tid;
    const int g = oct >= OCTS_PER_GSO;
    const int jq = (oct - g * OCTS_PER_GSO) * 2;   // first quad index in GSO g

    uint4 rc0 = make_uint4(0u, 0u, 0u, 0u);   // persistent packed row|col<<16
    uint4 rc1 = make_uint4(0u, 0u, 0u, 0u);

    // ---- P1: lvl1 (parent = e_0) + build bm1 + pack coords; block 0 inits out=b2 ----
    if (blk == 0 && tid < 512)
        out[tid] = __ldg(b2 + (tid & 127));
    if (act) {
        const int* eb = eidx + (size_t)g * 2 * N_EDGES;
        int4 ra = __ldg((const int4*)eb + jq);
        int4 rb = __ldg((const int4*)eb + jq + 1);
        int4 ca = __ldg((const int4*)(eb + N_EDGES) + jq);
        int4 cb = __ldg((const int4*)(eb + N_EDGES) + jq + 1);
        rc0.x = (unsigned)ra.x | ((unsigned)ca.x << 16);
        rc0.y = (unsigned)ra.y | ((unsigned)ca.y << 16);
        rc0.z = (unsigned)ra.z | ((unsigned)ca.z << 16);
        rc0.w = (unsigned)ra.w | ((unsigned)ca.w << 16);
        rc1.x = (unsigned)rb.x | ((unsigned)cb.x << 16);
        rc1.y = (unsigned)rb.y | ((unsigned)cb.y << 16);
        rc1.z = (unsigned)rb.z | ((unsigned)cb.z << 16);
        rc1.w = (unsigned)rb.w | ((unsigned)cb.w << 16);
        const int ri[8] = {ra.x, ra.y, ra.z, ra.w, rb.x, rb.y, rb.z, rb.w};
        const int ci[8] = {ca.x, ca.y, ca.z, ca.w, cb.x, cb.y, cb.z, cb.w};
        bool anyz = false;
#pragma unroll
        for (int i = 0; i < 8; i++) anyz |= (ri[i] == 0);
        if (anyz) {
            float* base = (float*)g_CL1 + g;
#pragma unroll
            for (int i = 0; i < 8; i++)
                if (ri[i] == 0) {
                    float v = __ldg(evals + (size_t)g * N_EDGES + jq * 4 + i);
                    atomicAdd(base + ci[i] * 2, v);
                    atomicOr(&g_bm1[ci[i] >> 5], 1u << (ci[i] & 31));
                }
        }
    }
    barrier_wait(NB);

    // ---- P2: lvl2 (bm1-filtered; coords from registers) + build bm2 ----
    if (tid < BM_WORDS) sbm[tid] = __ldg(&g_bm1[tid]);
    __syncthreads();
    if (act) {
        const unsigned pk[8] = {rc0.x, rc0.y, rc0.z, rc0.w, rc1.x, rc1.y, rc1.z, rc1.w};
        unsigned m = 0;
#pragma unroll
        for (int i = 0; i < 8; i++) {
            unsigned rr = pk[i] & 0xffffu;
            m |= (sbm[rr >> 5] >> (rr & 31)) & 1u ? (1u << i) : 0u;
        }
        if (m) {
            float* base = (float*)g_CL2 + 2 * g;
#pragma unroll
            for (int i = 0; i < 8; i++)
                if (m & (1u << i)) {
                    float2 qv = __ldg(g_CL1 + (pk[i] & 0xffffu));
                    if ((qv.x != 0.f) | (qv.y != 0.f)) {
                        unsigned cc = pk[i] >> 16;
                        float v = __ldg(evals + (size_t)g * N_EDGES + jq * 4 + i);
                        red2(base + cc * 4, v * qv.x, v * qv.y);
                        atomicOr(&g_bm2[cc >> 5], 1u << (cc & 31));
                    }
                }
        }
    }
    barrier_wait(NB);

    // ---- P3: lvl3 (bm2-filtered; 8 hoisted float4 gathers; red2 + red1) ----
    if (tid < BM_WORDS) sbm[tid] = __ldg(&g_bm2[tid]);
    __syncthreads();
    if (act) {
        const unsigned pk[8] = {rc0.x, rc0.y, rc0.z, rc0.w, rc1.x, rc1.y, rc1.z, rc1.w};
        unsigned m = 0;
#pragma unroll
        for (int i = 0; i < 8; i++) {
            unsigned rr = pk[i] & 0xffffu;
            m |= (sbm[rr >> 5] >> (rr & 31)) & 1u ? (1u << i) : 0u;
        }
        if (m) {
            float4 v0 = __ldg((const float4*)(evals + (size_t)g * N_EDGES) + jq);
            float4 v1 = __ldg((const float4*)(evals + (size_t)g * N_EDGES) + jq + 1);
            float4 qa[8];
#pragma unroll
            for (int i = 0; i < 8; i++)
                qa[i] = (m & (1u << i)) ? __ldg(g_CL2 + (pk[i] & 0xffffu)) : z4;
            const float vv[8] = {v0.x, v0.y, v0.z, v0.w, v1.x, v1.y, v1.z, v1.w};
#pragma unroll
            for (int i = 0; i < 8; i++)
                if (m & (1u << i)) {
                    float p0 = qa[i].x;                // R3 parent
                    float p1 = g ? qa[i].z : qa[i].y;  // R4 / R5 parent
                    float p2 = qa[i].w;                // R6 parent
                    unsigned cc = pk[i] >> 16;
                    if ((p0 != 0.f) | (p2 != 0.f))
                        red2((float*)&g_CL3p[g][cc], vv[i] * p0, vv[i] * p2);
                    if (p1 != 0.f)
                        red1(&g_CL3s[g][cc], vv[i] * p1);
                }
        }
    }
    barrier_wait(NB);

    // ---- P4: lvl4 (dense; 8 hoisted float2 gathers), then dot of the 12
    //          final slots + sigma + zero CL1/CL2/bm ----
    if (act) {
        float4 v0 = __ldg((const float4*)(evals + (size_t)g * N_EDGES) + jq);
        float4 v1 = __ldg((const float4*)(evals + (size_t)g * N_EDGES) + jq + 1);
        const float2* src = g_CL3p[g];
        const unsigned pk[8] = {rc0.x, rc0.y, rc0.z, rc0.w, rc1.x, rc1.y, rc1.z, rc1.w};
        float2 ga[8];
#pragma unroll
        for (int i = 0; i < 8; i++)
            ga[i] = __ldg(src + (pk[i] & 0xffffu));
        const float vv[8] = {v0.x, v0.y, v0.z, v0.w, v1.x, v1.y, v1.z, v1.w};
        float* base = (float*)g_CL4 + 2 * g;
#pragma unroll
        for (int i = 0; i < 8; i++)
            if ((ga[i].x != 0.f) | (ga[i].y != 0.f))
                red2(base + (pk[i] >> 16) * 4, vv[i] * ga[i].x, vv[i] * ga[i].y);
    }
    {
        int n0 = blk * DC;
        int lim = min(DC, N_NODES - n0);
        if (tid < lim) {
            int gn = n0 + tid;
            float2 a = __ldg(g_CL1 + gn);
            float4 c2 = __ldg(g_CL2 + gn);
            float2 p0 = __ldg(&g_CL3p[0][gn]);
            float s0v = __ldg(&g_CL3s[0][gn]);
            float2 p1 = __ldg(&g_CL3p[1][gn]);
            float s1v = __ldg(&g_CL3s[1][gn]);
            pool[0 * DC + tid] = a.x;   pool[1 * DC + tid] = a.y;
            pool[2 * DC + tid] = c2.x;  pool[3 * DC + tid] = c2.y;
            pool[4 * DC + tid] = c2.z;  pool[5 * DC + tid] = c2.w;
            pool[6 * DC + tid] = p0.x;  pool[7 * DC + tid] = p0.y;
            pool[8 * DC + tid] = s0v;
            pool[9 * DC + tid] = p1.x;  pool[10 * DC + tid] = p1.y;
            pool[11 * DC + tid] = s1v;
            // restore zeros (after loads; same thread = program order);
            // CL1/CL2 are not read by any other block in P4
            g_CL1[gn] = make_float2(0.f, 0.f);
            g_CL2[gn] = z4;
        }
        if (blk == 0 && tid >= 512 && tid < 512 + BM_WORDS) {
            g_bm1[tid - 512] = 0u;
            g_bm2[tid - 512] = 0u;
        }
        __syncthreads();
        if (tid < 128) {  // sigma: sig[1..4] = column sums of slots {0,2,1,5}
            const int slots[4] = {0, 2, 1, 5};
            int vi = tid >> 5, lane = tid & 31;
            float s = 0.f;
            for (int n = lane; n < lim; n += 32) s += pool[slots[vi] * DC + n];
#pragma unroll
            for (int off = 16; off; off >>= 1) s += __shfl_down_sync(0xffffffffu, s, off);
            if (lane == 0) atomicAdd(&g_sig[vi + 1], s);
        }
        int f = tid & 63;
        int bb = (tid >> 6) & 3;
        int vg = tid >> 8;  // 0..3, 3 slots each
        float a0 = 0.f, a1 = 0.f, a2 = 0.f;
        const float* xb = x + ((size_t)bb * N_NODES + n0) * 64 + f;
        const float* rsv = pool + vg * 3 * DC;
        for (int nn = 0; nn < lim; nn++) {
            float xv = __ldg(xb + (size_t)nn * 64);
            a0 += rsv[0 * DC + nn] * xv;
            a1 += rsv[1 * DC + nn] * xv;
            a2 += rsv[2 * DC + nn] * xv;
        }
        atomicAdd(&g_D[c_SVID[vg * 3 + 0]][bb][f], a0);
        atomicAdd(&g_D[c_SVID[vg * 3 + 1]][bb][f], a1);
        atomicAdd(&g_D[c_SVID[vg * 3 + 2]][bb][f], a2);
    }
    barrier_wait(NB);

    // ---- P5': blocks 0..15 early epilogue (pc2 in {0,1,3,4});
    //           blocks 16..147 dot of the 4 CL4 slots + zero CL3/CL4 ----
    if (blk < 16) {
        epi_unit(blk & 3, c_PC2A[blk >> 2], x, W1, b1, W2, out, pool);
    } else {
        int lblk = blk - 16;
        int n0 = lblk * DC5;
        int lim = min(DC5, N_NODES - n0);
        if (lim > 0 && tid < lim) {
            int gn = n0 + tid;
            float4 c4 = __ldg(g_CL4 + gn);
            pool[0 * DC5 + tid] = c4.x; pool[1 * DC5 + tid] = c4.y;
            pool[2 * DC5 + tid] = c4.z; pool[3 * DC5 + tid] = c4.w;
            g_CL4[gn] = z4;
            g_CL3p[0][gn] = make_float2(0.f, 0.f);
            g_CL3p[1][gn] = make_float2(0.f, 0.f);
            g_CL3s[0][gn] = 0.f;
            g_CL3s[1][gn] = 0.f;
        }
        __syncthreads();
        if (lim > 0) {
            int f = tid & 63;
            int bb = (tid >> 6) & 3;
            int vg = tid >> 8;  // 0..3, 1 slot each
            float a0 = 0.f;
            const float* xb = x + ((size_t)bb * N_NODES + n0) * 64 + f;
            const float* rsv = pool + vg * DC5;
            for (int nn = 0; nn < lim; nn++)
                a0 += rsv[nn] * __ldg(xb + (size_t)nn * 64);
            atomicAdd(&g_D[c_SVID[12 + vg]][bb][f], a0);
        }
    }
    if (blk >= 8) { barrier_arrive(NB); return; }
    barrier_wait(NB);

    // ---- PE2: blocks 0..7 = (b, pc2 in {2,5}) -> T[2]/T[4] + out ----
    epi_unit(blk & 3, (blk >> 2) ? 5 : 2, x, W1, b1, W2, out, pool);
    barrier_wait(8);
    // zero D and sig (read in epilogue; safe only after the 8-block barrier)
    for (int i = blk * NT + tid; i < 17 * 4 * 64; i += 8 * NT) (&g_D[0][0][0])[i] = 0.f;
    if (blk == 0 && tid < 5) g_sig[tid] = 0.f;
}

extern "C" void kernel_launch(void* const* d_in, const int* in_sizes, int n_in,
                              void* d_out, int out_size) {
    const float* x = nullptr;
    const int* eidx = nullptr;
    const float* evals = nullptr;
    const float *W1 = nullptr, *b1 = nullptr, *W2 = nullptr, *b2 = nullptr;
    for (int i = 0; i < n_in; i++) {
        switch (in_sizes[i]) {
            case 2560000: x = (const float*)d_in[i]; break;
            case 1280000: eidx = (const int*)d_in[i]; break;
            case 640000:  evals = (const float*)d_in[i]; break;
            case 49152:   W1 = (const float*)d_in[i]; break;
            case 98304:   W2 = (const float*)d_in[i]; break;
            case 128:
                if (!b1) b1 = (const float*)d_in[i];
                else b2 = (const float*)d_in[i];
                break;
        }
    }
    float* out = (float*)d_out;
    fused_kernel<<<NB, NT>>>(eidx, evals, x, W1, b1, W2, b2, out);
}

// round 17
// speedup vs baseline: 1.0560x; 1.0560x over previous
#include <cuda_runtime.h>

#define N_NODES 10000
#define N_EDGES 320000
#define QUADS (N_EDGES / 4)      // 80000 per GSO
#define OCTS_PER_GSO (N_EDGES / 8)  // 40000
#define NOCT (2 * OCTS_PER_GSO)     // 80000
#define NB 148
#define NT 1024
#define BM_WORDS 320
#define DC 68       // P4 dot chunk: 148 blocks x 68 >= 10000
#define DC5 76      // P5' dot chunk: 132 blocks x 76 >= 10000
#define OPB 541     // octs per block: 148*541 >= 80000 (last block partial)

// INVARIANT: accumulated scratch (CL*, bm*, D, sig) is ZERO at kernel entry
// and restored to ZERO before exit. L1-cached __ldg of data written earlier in
// this launch is safe: L1 is flushed at launch boundaries, global stores and
// atomics don't allocate in L1, and no array is regular-loaded before its
// producer phase's barrier. Each thread owns ONE oct (8 edges, single GSO) in
// every scan phase; its packed coords live in registers for the whole kernel.
__device__ float2 g_CL1[N_NODES];      // {R1, R2}
__device__ float4 g_CL2[N_NODES];      // {R3, R5, R4, R6}
__device__ float2 g_CL3p[2][N_NODES];  // GSO0: {R7, R11}; GSO1: {R8, R12}  (lvl4 gathers)
__device__ float  g_CL3s[2][N_NODES];  // GSO0: R10;       GSO1: R9        (dot only)
__device__ float4 g_CL4[N_NODES];      // {R13, R15, R14, R16}
__device__ unsigned g_bm1[BM_WORDS];
__device__ unsigned g_bm2[BM_WORDS];
__device__ float g_D[17][4][64];
__device__ float g_sig[5];
__device__ int g_count;             // returns to 0 at each barrier
__device__ volatile int g_gen;      // monotonic; equality-compare only

__constant__ int c_VEC_ID[5][5] = {
    {0, 1, 3, 2, 6},
    {1, 3, 7, 4, 9},
    {3, 7, 13, 8, 14},
    {2, 5, 10, 6, 12},
    {6, 11, 15, 12, 16}};
// pool slots: CL1.xy, CL2.xyzw, CL3p0.xy, CL3s0, CL3p1.xy, CL3s1, CL4.xyzw
__constant__ int c_SVID[16] = {1, 2, 3, 5, 4, 6, 7, 11, 10, 8, 12, 9, 13, 15, 14, 16};
__constant__ int c_PC2A[4] = {0, 1, 3, 4};  // early-epilogue pc2 (si in {0,1,0,3})

__device__ __forceinline__ void red1(float* p, float a) {
    asm volatile("red.global.add.f32 [%0], %1;" :: "l"(p), "f"(a) : "memory");
}
__device__ __forceinline__ void red2(float* p, float a, float b) {
    asm volatile("red.global.add.v2.f32 [%0], {%1,%2};" :: "l"(p), "f"(a), "f"(b) : "memory");
}

__device__ __forceinline__ void barrier_arrive(int target) {
    __syncthreads();
    if (threadIdx.x == 0) {
        __threadfence();
        int gen = g_gen;
        if (atomicAdd(&g_count, 1) == target - 1) {
            g_count = 0;
            __threadfence();
            g_gen = gen + 1;
        }
    }
}
__device__ __forceinline__ void barrier_wait(int target) {
    __syncthreads();
    if (threadIdx.x == 0) {
        __threadfence();
        int gen = g_gen;
        if (atomicAdd(&g_count, 1) == target - 1) {
            g_count = 0;
            __threadfence();
            g_gen = gen + 1;
        } else {
            while (g_gen == gen) { }
        }
    }
    __syncthreads();
}

// Full epilogue unit for one (b, pc2): T[si] in smem, then out += T @ W2[pc2].
__device__ __forceinline__ void epi_unit(
    int b, int pc2, const float* __restrict__ x,
    const float* __restrict__ W1, const float* __restrict__ b1,
    const float* __restrict__ W2, float* __restrict__ out, float* pool) {
    int e2 = pc2 / 3, k2 = pc2 % 3;
    int si = (k2 == 0) ? 0 : (e2 * 2 + k2);
    float sg = (si == 0) ? 1.0f : __ldg(&g_sig[si]);
    int g = threadIdx.x & 127, fo = threadIdx.x >> 7;  // 8 f-groups
    float* Tl = pool + 1024;
    float acc = 0.f;
#pragma unroll
    for (int pc1 = 0; pc1 < 6; pc1++) {
        int e1 = pc1 / 3, k1 = pc1 % 3;
        int pi = (k1 == 0) ? 0 : (e1 * 2 + k1);
        int vid = c_VEC_ID[si][pi];
        const float* Dp = vid ? &g_D[vid][b][0] : (x + (size_t)b * N_NODES * 64);
        const float* Wp = W1 + (size_t)pc1 * 64 * 128;
#pragma unroll
        for (int i = 0; i < 8; i++) {
            int f = fo * 8 + i;
            acc += __ldg(Dp + f) * __ldg(Wp + (size_t)f * 128 + g);
        }
    }
    pool[fo * 128 + g] = acc;
    __syncthreads();
    if (fo == 0) {
        float s = sg * __ldg(b1 + g);
#pragma unroll
        for (int i = 0; i < 8; i++) s += pool[i * 128 + g];
        Tl[g] = s;
    }
    __syncthreads();
    const float* Wp2 = W2 + (size_t)pc2 * 128 * 128;
    float acc2 = 0.f;
#pragma unroll
    for (int i = 0; i < 16; i++) {
        int f = fo * 16 + i;
        acc2 += Tl[f] * __ldg(Wp2 + (size_t)f * 128 + g);
    }
    __syncthreads();
    pool[fo * 128 + g] = acc2;
    __syncthreads();
    if (fo == 0) {
        float s = 0.f;
#pragma unroll
        for (int i = 0; i < 8; i++) s += pool[i * 128 + g];
        atomicAdd(out + (size_t)b * 128 + g, s);
    }
}

__global__ void __launch_bounds__(NT, 1)
fused_kernel(const int* __restrict__ eidx, const float* __restrict__ evals,
             const float* __restrict__ x,
             const float* __restrict__ W1, const float* __restrict__ b1,
             const float* __restrict__ W2, const float* __restrict__ b2,
             float* __restrict__ out) {
    __shared__ __align__(16) float pool[1920];
    __shared__ unsigned sbm[BM_WORDS];

    const int tid = threadIdx.x;
    const int blk = blockIdx.x;
    const float4 z4 = make_float4(0.f, 0.f, 0.f, 0.f);

    // One oct (8 edges, quads jq and jq+1, single GSO) per thread, all phases.
    const int ostart = blk * OPB;
    const int ocount = min(OPB, NOCT - ostart);
    const bool act = tid < ocount;
    const int oct = ostart + tid;
    const int g = oct >= OCTS_PER_GSO;
    const int jq = (oct - g * OCTS_PER_GSO) * 2;   // first quad index in GSO g

    uint4 rc0 = make_uint4(0u, 0u, 0u, 0u);   // persistent packed row|col<<16
    uint4 rc1 = make_uint4(0u, 0u, 0u, 0u);

    // ---- P1: lvl1 (parent = e_0) + build bm1 + pack coords; block 0 inits out=b2 ----
    if (blk == 0 && tid < 512)
        out[tid] = __ldg(b2 + (tid & 127));
    if (act) {
        const int* eb = eidx + (size_t)g * 2 * N_EDGES;
        int4 ra = __ldg((const int4*)eb + jq);
        int4 rb = __ldg((const int4*)eb + jq + 1);
        int4 ca = __ldg((const int4*)(eb + N_EDGES) + jq);
        int4 cb = __ldg((const int4*)(eb + N_EDGES) + jq + 1);
        rc0.x = (unsigned)ra.x | ((unsigned)ca.x << 16);
        rc0.y = (unsigned)ra.y | ((unsigned)ca.y << 16);
        rc0.z = (unsigned)ra.z | ((unsigned)ca.z << 16);
        rc0.w = (unsigned)ra.w | ((unsigned)ca.w << 16);
        rc1.x = (unsigned)rb.x | ((unsigned)cb.x << 16);
        rc1.y = (unsigned)rb.y | ((unsigned)cb.y << 16);
        rc1.z = (unsigned)rb.z | ((unsigned)cb.z << 16);
        rc1.w = (unsigned)rb.w | ((unsigned)cb.w << 16);
        const int ri[8] = {ra.x, ra.y, ra.z, ra.w, rb.x, rb.y, rb.z, rb.w};
        const int ci[8] = {ca.x, ca.y, ca.z, ca.w, cb.x, cb.y, cb.z, cb.w};
        bool anyz = false;
#pragma unroll
        for (int i = 0; i < 8; i++) anyz |= (ri[i] == 0);
        if (anyz) {
            float* base = (float*)g_CL1 + g;
#pragma unroll
            for (int i = 0; i < 8; i++)
                if (ri[i] == 0) {
                    float v = __ldg(evals + (size_t)g * N_EDGES + jq * 4 + i);
                    atomicAdd(base + ci[i] * 2, v);
                    atomicOr(&g_bm1[ci[i] >> 5], 1u << (ci[i] & 31));
                }
        }
    }
    barrier_wait(NB);

    // ---- P2: lvl2 (bm1-filtered; coords from registers) + build bm2 ----
    if (tid < BM_WORDS) sbm[tid] = __ldg(&g_bm1[tid]);
    __syncthreads();
    if (act) {
        const unsigned pk[8] = {rc0.x, rc0.y, rc0.z, rc0.w, rc1.x, rc1.y, rc1.z, rc1.w};
        unsigned m = 0;
#pragma unroll
        for (int i = 0; i < 8; i++) {
            unsigned rr = pk[i] & 0xffffu;
            m |= (sbm[rr >> 5] >> (rr & 31)) & 1u ? (1u << i) : 0u;
        }
        if (m) {
            float* base = (float*)g_CL2 + 2 * g;
#pragma unroll
            for (int i = 0; i < 8; i++)
                if (m & (1u << i)) {
                    float2 qv = __ldg(g_CL1 + (pk[i] & 0xffffu));
                    if ((qv.x != 0.f) | (qv.y != 0.f)) {
                        unsigned cc = pk[i] >> 16;
                        float v = __ldg(evals + (size_t)g * N_EDGES + jq * 4 + i);
                        red2(base + cc * 4, v * qv.x, v * qv.y);
                        atomicOr(&g_bm2[cc >> 5], 1u << (cc & 31));
                    }
                }
        }
    }
    barrier_wait(NB);

    // ---- P3: lvl3 (bm2-filtered; 8 hoisted float4 gathers; red2 + red1) ----
    if (tid < BM_WORDS) sbm[tid] = __ldg(&g_bm2[tid]);
    __syncthreads();
    if (act) {
        const unsigned pk[8] = {rc0.x, rc0.y, rc0.z, rc0.w, rc1.x, rc1.y, rc1.z, rc1.w};
        unsigned m = 0;
#pragma unroll
        for (int i = 0; i < 8; i++) {
            unsigned rr = pk[i] & 0xffffu;
            m |= (sbm[rr >> 5] >> (rr & 31)) & 1u ? (1u << i) : 0u;
        }
        if (m) {
            float4 v0 = __ldg((const float4*)(evals + (size_t)g * N_EDGES) + jq);
            float4 v1 = __ldg((const float4*)(evals + (size_t)g * N_EDGES) + jq + 1);
            float4 qa[8];
#pragma unroll
            for (int i = 0; i < 8; i++)
                qa[i] = (m & (1u << i)) ? __ldg(g_CL2 + (pk[i] & 0xffffu)) : z4;
            const float vv[8] = {v0.x, v0.y, v0.z, v0.w, v1.x, v1.y, v1.z, v1.w};
#pragma unroll
            for (int i = 0; i < 8; i++)
                if (m & (1u << i)) {
                    float p0 = qa[i].x;                // R3 parent
                    float p1 = g ? qa[i].z : qa[i].y;  // R4 / R5 parent
                    float p2 = qa[i].w;                // R6 parent
                    unsigned cc = pk[i] >> 16;
                    if ((p0 != 0.f) | (p2 != 0.f))
                        red2((float*)&g_CL3p[g][cc], vv[i] * p0, vv[i] * p2);
                    if (p1 != 0.f)
                        red1(&g_CL3s[g][cc], vv[i] * p1);
                }
        }
    }
    barrier_wait(NB);

    // ---- P4: warps 0..16 lvl4 scan; warps 17..24 (256 thr) CONCURRENT dot of
    //          the 12 final slots + sigma + zero CL1/CL2; warps 25+ zero bm ----
    if (act) {
        float4 v0 = __ldg((const float4*)(evals + (size_t)g * N_EDGES) + jq);
        float4 v1 = __ldg((const float4*)(evals + (size_t)g * N_EDGES) + jq + 1);
        const float2* src = g_CL3p[g];
        const unsigned pk[8] = {rc0.x, rc0.y, rc0.z, rc0.w, rc1.x, rc1.y, rc1.z, rc1.w};
        float2 ga[8];
#pragma unroll
        for (int i = 0; i < 8; i++)
            ga[i] = __ldg(src + (pk[i] & 0xffffu));
        const float vv[8] = {v0.x, v0.y, v0.z, v0.w, v1.x, v1.y, v1.z, v1.w};
        float* base = (float*)g_CL4 + 2 * g;
#pragma unroll
        for (int i = 0; i < 8; i++)
            if ((ga[i].x != 0.f) | (ga[i].y != 0.f))
                red2(base + (pk[i] >> 16) * 4, vv[i] * ga[i].x, vv[i] * ga[i].y);
    } else if (tid >= 544 && tid < 800) {
        // dot group: reads CL1..CL3 (final since P3 barrier) + x; private chunk
        const int idx = tid - 544;
        const int n0 = blk * DC;
        const int lim = min(DC, N_NODES - n0);
        if (idx < lim) {
            int gn = n0 + idx;
            float2 a = __ldg(g_CL1 + gn);
            float4 c2 = __ldg(g_CL2 + gn);
            float2 p0 = __ldg(&g_CL3p[0][gn]);
            float s0v = __ldg(&g_CL3s[0][gn]);
            float2 p1 = __ldg(&g_CL3p[1][gn]);
            float s1v = __ldg(&g_CL3s[1][gn]);
            pool[0 * DC + idx] = a.x;   pool[1 * DC + idx] = a.y;
            pool[2 * DC + idx] = c2.x;  pool[3 * DC + idx] = c2.y;
            pool[4 * DC + idx] = c2.z;  pool[5 * DC + idx] = c2.w;
            pool[6 * DC + idx] = p0.x;  pool[7 * DC + idx] = p0.y;
            pool[8 * DC + idx] = s0v;
            pool[9 * DC + idx] = p1.x;  pool[10 * DC + idx] = p1.y;
            pool[11 * DC + idx] = s1v;
            // restore zeros (after loads; same thread = program order);
            // CL1/CL2 are not read by any other block in P4
            g_CL1[gn] = make_float2(0.f, 0.f);
            g_CL2[gn] = z4;
        }
        asm volatile("bar.sync 1, 256;" ::: "memory");  // warps 17..24 only
        if (idx < 128) {  // sigma: sig[1..4] = column sums of slots {0,2,1,5}
            const int slots[4] = {0, 2, 1, 5};
            int vi = idx >> 5, lane = idx & 31;
            float s = 0.f;
            for (int n = lane; n < lim; n += 32) s += pool[slots[vi] * DC + n];
#pragma unroll
            for (int off = 16; off; off >>= 1) s += __shfl_down_sync(0xffffffffu, s, off);
            if (lane == 0) atomicAdd(&g_sig[vi + 1], s);
        }
        int f = idx & 63;
        int bb = idx >> 6;
        float acc[12];
#pragma unroll
        for (int s = 0; s < 12; s++) acc[s] = 0.f;
        const float* xb = x + ((size_t)bb * N_NODES + n0) * 64 + f;
        for (int nn = 0; nn < lim; nn++) {
            float xv = __ldg(xb + (size_t)nn * 64);
#pragma unroll
            for (int s = 0; s < 12; s++) acc[s] += pool[s * DC + nn] * xv;
        }
#pragma unroll
        for (int s = 0; s < 12; s++) atomicAdd(&g_D[c_SVID[s]][bb][f], acc[s]);
    } else if (blk == 0 && tid >= 800 && tid < 800 + BM_WORDS) {
        g_bm1[tid - 800] = 0u;
        g_bm2[tid - 800] = 0u;
    }
    barrier_wait(NB);

    // ---- P5': blocks 0..15 early epilogue (pc2 in {0,1,3,4});
    //           blocks 16..147 dot of the 4 CL4 slots + zero CL3/CL4 ----
    if (blk < 16) {
        epi_unit(blk & 3, c_PC2A[blk >> 2], x, W1, b1, W2, out, pool);
    } else {
        int lblk = blk - 16;
        int n0 = lblk * DC5;
        int lim = min(DC5, N_NODES - n0);
        if (lim > 0 && tid < lim) {
            int gn = n0 + tid;
            float4 c4 = __ldg(g_CL4 + gn);
            pool[0 * DC5 + tid] = c4.x; pool[1 * DC5 + tid] = c4.y;
            pool[2 * DC5 + tid] = c4.z; pool[3 * DC5 + tid] = c4.w;
            g_CL4[gn] = z4;
            g_CL3p[0][gn] = make_float2(0.f, 0.f);
            g_CL3p[1][gn] = make_float2(0.f, 0.f);
            g_CL3s[0][gn] = 0.f;
            g_CL3s[1][gn] = 0.f;
        }
        __syncthreads();
        if (lim > 0) {
            int f = tid & 63;
            int bb = (tid >> 6) & 3;
            int vg = tid >> 8;  // 0..3, 1 slot each
            float a0 = 0.f;
            const float* xb = x + ((size_t)bb * N_NODES + n0) * 64 + f;
            const float* rsv = pool + vg * DC5;
            for (int nn = 0; nn < lim; nn++)
                a0 += rsv[nn] * __ldg(xb + (size_t)nn * 64);
            atomicAdd(&g_D[c_SVID[12 + vg]][bb][f], a0);
        }
    }
    if (blk >= 8) { barrier_arrive(NB); return; }
    barrier_wait(NB);

    // ---- PE2: blocks 0..7 = (b, pc2 in {2,5}) -> T[2]/T[4] + out ----
    epi_unit(blk & 3, (blk >> 2) ? 5 : 2, x, W1, b1, W2, out, pool);
    barrier_wait(8);
    // zero D and sig (read in epilogue; safe only after the 8-block barrier)
    for (int i = blk * NT + tid; i < 17 * 4 * 64; i += 8 * NT) (&g_D[0][0][0])[i] = 0.f;
    if (blk == 0 && tid < 5) g_sig[tid] = 0.f;
}

extern "C" void kernel_launch(void* const* d_in, const int* in_sizes, int n_in,
                              void* d_out, int out_size) {
    const float* x = nullptr;
    const int* eidx = nullptr;
    const float* evals = nullptr;
    const float *W1 = nullptr, *b1 = nullptr, *W2 = nullptr, *b2 = nullptr;
    for (int i = 0; i < n_in; i++) {
        switch (in_sizes[i]) {
            case 2560000: x = (const float*)d_in[i]; break;
            case 1280000: eidx = (const int*)d_in[i]; break;
            case 640000:  evals = (const float*)d_in[i]; break;
            case 49152:   W1 = (const float*)d_in[i]; break;
            case 98304:   W2 = (const float*)d_in[i]; break;
            case 128:
                if (!b1) b1 = (const float*)d_in[i];
                else b2 = (const float*)d_in[i];
                break;
        }
    }
    float* out = (float*)d_out;
    fused_kernel<<<NB, NT>>>(eidx, evals, x, W1, b1, W2, b2, out);
}